// round 12
// baseline (speedup 1.0000x reference)
#include <cuda_runtime.h>
#include <cstdint>

typedef unsigned long long u64;

__device__ __forceinline__ u64 pack2(float lo, float hi) {
    u64 r; asm("mov.b64 %0, {%1, %2};" : "=l"(r) : "f"(lo), "f"(hi)); return r;
}
__device__ __forceinline__ void unpack2(u64 v, float& lo, float& hi) {
    asm("mov.b64 {%0, %1}, %2;" : "=f"(lo), "=f"(hi) : "l"(v));
}
__device__ __forceinline__ u64 ffma2(u64 a, u64 b, u64 c) {
    u64 d; asm("fma.rn.f32x2 %0, %1, %2, %3;" : "=l"(d) : "l"(a), "l"(b), "l"(c)); return d;
}
__device__ __forceinline__ void red4(float* addr, float a, float b, float c, float d) {
    asm volatile("red.global.add.v4.f32 [%0], {%1, %2, %3, %4};"
                 :: "l"(addr), "f"(a), "f"(b), "f"(c), "f"(d) : "memory");
}
__device__ __forceinline__ uint32_t tf32c(float f) {
    uint32_t u; asm("cvt.rna.tf32.f32 %0, %1;" : "=r"(u) : "f"(f)); return u;
}
// D(16x8) += A(16x8,row) * B(8x8,col)  [tf32, fp32 accum]
__device__ __forceinline__ void mma8(float d[4],
    uint32_t a0, uint32_t a1, uint32_t a2, uint32_t a3, uint32_t b0, uint32_t b1) {
    asm volatile("mma.sync.aligned.m16n8k8.row.col.f32.tf32.tf32.f32 "
        "{%0,%1,%2,%3}, {%4,%5,%6,%7}, {%8,%9}, {%0,%1,%2,%3};"
        : "+f"(d[0]), "+f"(d[1]), "+f"(d[2]), "+f"(d[3])
        : "r"(a0), "r"(a1), "r"(a2), "r"(a3), "r"(b0), "r"(b1));
}

#define BB 16
#define NPIX 1024
#define DD 128
#define KK 32
#define CHUNKS 32
#define ROWS_CTA 32
#define NTHREADS 256
#define STR 132              // padded row stride (floats): conflict-free frag loads

__global__ void zero_kernel(float4* out, int n4) {
    int i = blockIdx.x * blockDim.x + threadIdx.x;
    if (i < n4) out[i] = make_float4(0.f, 0.f, 0.f, 0.f);
}

__global__ void __launch_bounds__(NTHREADS, 5) enc_kernel(
    const float* __restrict__ x, const float* __restrict__ cw,
    const float* __restrict__ scale, float* __restrict__ out)
{
    __shared__ __align__(16) float XF[ROWS_CTA * STR];   // fp32 x tile
    __shared__ __align__(16) float CF[KK * STR];         // fp32 codewords
    __shared__ float As[ROWS_CTA * 33];                  // exp then normalized A
    __shared__ float x2s[ROWS_CTA];
    __shared__ float ps[ROWS_CTA * 4];                   // per-(row, n-tile) exp sums
    __shared__ float p1[KK], p2[KK], p3[KK];

    const int t = threadIdx.x, lane = t & 31, w = t >> 5;   // w: 0..7
    const int b = blockIdx.y, chunk = blockIdx.x;

    // ================= stage: x + c (fp32, padded), x2/c2 from registers =================
    {
        const float4* xg = (const float4*)(x + ((size_t)b * NPIX + chunk * ROWS_CTA) * DD);
        const float4* cg = (const float4*)cw;
        float q[4], qc[4];
        #pragma unroll
        for (int p = 0; p < 4; p++) {
            float4 v = xg[p * NTHREADS + t];            // row = 8p + w, col = 4*lane
            *(float4*)&XF[(8 * p + w) * STR + 4 * lane] = v;
            float s = v.x * v.x; s = fmaf(v.y, v.y, s);
            s = fmaf(v.z, v.z, s); q[p] = fmaf(v.w, v.w, s);

            float4 c = cg[p * NTHREADS + t];            // k = 8p + w, col = 4*lane
            *(float4*)&CF[(8 * p + w) * STR + 4 * lane] = c;
            float u = c.x * c.x; u = fmaf(c.y, c.y, u);
            u = fmaf(c.z, c.z, u); qc[p] = fmaf(c.w, c.w, u);
        }
        #pragma unroll
        for (int off = 16; off > 0; off >>= 1) {
            #pragma unroll
            for (int p = 0; p < 4; p++) {
                q[p]  += __shfl_xor_sync(0xffffffffu, q[p], off);
                qc[p] += __shfl_xor_sync(0xffffffffu, qc[p], off);
            }
        }
        if (lane == 0) {
            #pragma unroll
            for (int p = 0; p < 4; p++) {
                int k = 8 * p + w;
                x2s[k] = q[p];
                float s = scale[k];
                p1[k] = s; p2[k] = -2.f * s; p3[k] = s * qc[p];
            }
        }
    }
    __syncthreads();

    // ========== dot phase: 3xTF32 mma, fragments built on the fly from fp32 ==========
    // warp = (rt = w>>2 row-tile of 16, nt = w&3 n-tile of 8 k's), all 16 c-steps
    {
        const int rt = w >> 2, nt = w & 3;
        const int gid = lane >> 2, tig = lane & 3;
        const int r0 = 16 * rt + gid, r1 = r0 + 8;
        const int kb = 8 * nt + gid;
        const float* xf0 = &XF[r0 * STR];
        const float* xf1 = &XF[r1 * STR];
        const float* cf  = &CF[kb * STR];

        float dHH[4] = {0.f, 0.f, 0.f, 0.f};
        float dHL[4] = {0.f, 0.f, 0.f, 0.f};
        float dLH[4] = {0.f, 0.f, 0.f, 0.f};

        #pragma unroll
        for (int c = 0; c < 16; c++) {
            const int cb = c * 8;
            float af0 = xf0[cb + tig],     af1 = xf1[cb + tig];
            float af2 = xf0[cb + tig + 4], af3 = xf1[cb + tig + 4];
            uint32_t ah0 = tf32c(af0), ah1 = tf32c(af1);
            uint32_t ah2 = tf32c(af2), ah3 = tf32c(af3);
            uint32_t al0 = tf32c(af0 - __uint_as_float(ah0));
            uint32_t al1 = tf32c(af1 - __uint_as_float(ah1));
            uint32_t al2 = tf32c(af2 - __uint_as_float(ah2));
            uint32_t al3 = tf32c(af3 - __uint_as_float(ah3));
            float bf0 = cf[cb + tig], bf1 = cf[cb + tig + 4];
            uint32_t bh0 = tf32c(bf0), bh1 = tf32c(bf1);
            uint32_t bl0 = tf32c(bf0 - __uint_as_float(bh0));
            uint32_t bl1 = tf32c(bf1 - __uint_as_float(bh1));
            mma8(dHH, ah0, ah1, ah2, ah3, bh0, bh1);
            mma8(dHL, ah0, ah1, ah2, ah3, bl0, bl1);
            mma8(dLH, al0, al1, al2, al3, bh0, bh1);
        }
        float d[4];
        #pragma unroll
        for (int j = 0; j < 4; j++) d[j] = (dHH[j] + dHL[j]) + dLH[j];

        // ---- exp + per-(row, n-tile) sums (no max-subtraction: scale<0,
        //      logits bounded; validated rel_err ~2.5e-7 across rounds) ----
        const float x20 = x2s[r0], x21 = x2s[r1];
        float s0 = 0.f, s1 = 0.f;
        #pragma unroll
        for (int p = 0; p < 2; p++) {
            int k = 8 * nt + 2 * tig + p;
            float P1 = p1[k], P2 = p2[k], P3 = p3[k];
            float e0 = __expf(fmaf(P1, x20, fmaf(P2, d[p],     P3)));
            float e1 = __expf(fmaf(P1, x21, fmaf(P2, d[2 + p], P3)));
            As[r0 * 33 + k] = e0;
            As[r1 * 33 + k] = e1;
            s0 += e0; s1 += e1;
        }
        s0 += __shfl_xor_sync(0xffffffffu, s0, 1);
        s0 += __shfl_xor_sync(0xffffffffu, s0, 2);
        s1 += __shfl_xor_sync(0xffffffffu, s1, 1);
        s1 += __shfl_xor_sync(0xffffffffu, s1, 2);
        if (tig == 0) { ps[r0 * 4 + nt] = s0; ps[r1 * 4 + nt] = s1; }
    }
    __syncthreads();

    // ================= normalize A in place =================
    #pragma unroll
    for (int j = 0; j < 4; j++) {
        int r = 8 * j + w;
        float rinv = __fdividef(1.f, (ps[4 * r] + ps[4 * r + 1]) + (ps[4 * r + 2] + ps[4 * r + 3]));
        As[r * 33 + lane] *= rinv;
    }
    __syncthreads();

    // ================= E accumulate: k = lane, d slab [16w, 16w+16) =================
    u64 acc[8] = {0ull, 0ull, 0ull, 0ull, 0ull, 0ull, 0ull, 0ull};
    float Sk = 0.f;
    #pragma unroll 4
    for (int r = 0; r < ROWS_CTA; r++) {
        float av = As[r * 33 + lane];
        Sk += av;
        u64 pa = pack2(av, av);
        const ulonglong2* xp = (const ulonglong2*)&XF[r * STR + 16 * w];
        ulonglong2 v0 = xp[0], v1 = xp[1], v2 = xp[2], v3 = xp[3];
        acc[0] = ffma2(pa, v0.x, acc[0]);
        acc[1] = ffma2(pa, v0.y, acc[1]);
        acc[2] = ffma2(pa, v1.x, acc[2]);
        acc[3] = ffma2(pa, v1.y, acc[3]);
        acc[4] = ffma2(pa, v2.x, acc[4]);
        acc[5] = ffma2(pa, v2.y, acc[5]);
        acc[6] = ffma2(pa, v3.x, acc[6]);
        acc[7] = ffma2(pa, v3.y, acc[7]);
    }
    const float nSk = -Sk;

    float a[16];
    #pragma unroll
    for (int j = 0; j < 8; j++) unpack2(acc[j], a[2 * j], a[2 * j + 1]);

    // codewords for the correction read from global (L2-hot, 16KB total)
    const float4* cg4 = (const float4*)(cw + (size_t)lane * DD + 16 * w);
    float* ob = out + ((size_t)(b * KK + lane)) * DD + 16 * w;
    #pragma unroll
    for (int j = 0; j < 4; j++) {
        float4 c = cg4[j];
        red4(&ob[4 * j],
             fmaf(nSk, c.x, a[4 * j + 0]),
             fmaf(nSk, c.y, a[4 * j + 1]),
             fmaf(nSk, c.z, a[4 * j + 2]),
             fmaf(nSk, c.w, a[4 * j + 3]));
    }
}

extern "C" void kernel_launch(void* const* d_in, const int* in_sizes, int n_in,
                              void* d_out, int out_size) {
    const float* x  = (const float*)d_in[0];
    const float* cw = (const float*)d_in[1];
    const float* sc = (const float*)d_in[2];
    float* out = (float*)d_out;

    int n4 = out_size / 4;                 // 16384 float4
    zero_kernel<<<(n4 + 255) / 256, 256>>>((float4*)out, n4);

    dim3 grid(CHUNKS, BB);
    enc_kernel<<<grid, NTHREADS>>>(x, cw, sc, out);
}

// round 13
// speedup vs baseline: 1.3928x; 1.3928x over previous
#include <cuda_runtime.h>
#include <cstdint>

__device__ __forceinline__ uint32_t tf32c(float f) {
    uint32_t u; asm("cvt.rna.tf32.f32 %0, %1;" : "=r"(u) : "f"(f)); return u;
}
__device__ __forceinline__ void red2(float* addr, float a, float b) {
    asm volatile("red.global.add.v2.f32 [%0], {%1, %2};"
                 :: "l"(addr), "f"(a), "f"(b) : "memory");
}
// D(16x8) += A(16x8,row) * B(8x8,col)  [tf32, fp32 accum]
__device__ __forceinline__ void mma8(float d[4],
    uint32_t a0, uint32_t a1, uint32_t a2, uint32_t a3, uint32_t b0, uint32_t b1) {
    asm volatile("mma.sync.aligned.m16n8k8.row.col.f32.tf32.tf32.f32 "
        "{%0,%1,%2,%3}, {%4,%5,%6,%7}, {%8,%9}, {%0,%1,%2,%3};"
        : "+f"(d[0]), "+f"(d[1]), "+f"(d[2]), "+f"(d[3])
        : "r"(a0), "r"(a1), "r"(a2), "r"(a3), "r"(b0), "r"(b1));
}

#define BB 16
#define NPIX 1024
#define DD 128
#define KK 32
#define CHUNKS 8
#define ROWS_CTA 128
#define NTHREADS 512
#define STR 132     // XH/XL/CH/CL row stride (u32): conflict-free (4g+t) frag loads
#define AST 40      // As row stride (floats): conflict-free (8t+g) A-frag loads

// dynamic smem layout (bytes)
#define O_XH  0                          // tf32 x-hi [128][132] u32   67584
#define O_XL  67584                      // tf32 x-lo                  67584
#define O_CH  135168                     // tf32 c-hi [32][132]        16896
#define O_CL  152064                     // tf32 c-lo                  16896
#define O_AS  168960                     // A [128][40] f32            20480
#define O_X2  189440                     // x2 [128]                   512
#define O_PS  189952                     // half-row exp sums [128][2] 1024
#define O_P1  190976
#define O_P2  191104
#define O_P3  191232
#define O_SKS 191360                     // Sk partials [16][32]       2048
#define O_SK  193408                     // Sk [32]                    128
#define SMEM_TOTAL 193536

__global__ void zero_kernel(float4* out, int n4) {
    int i = blockIdx.x * blockDim.x + threadIdx.x;
    if (i < n4) out[i] = make_float4(0.f, 0.f, 0.f, 0.f);
}

__global__ void __launch_bounds__(NTHREADS) enc_kernel(
    const float* __restrict__ x, const float* __restrict__ cw,
    const float* __restrict__ scale, float* __restrict__ out)
{
    extern __shared__ __align__(16) char sm[];
    uint32_t* XH = (uint32_t*)(sm + O_XH);
    uint32_t* XL = (uint32_t*)(sm + O_XL);
    uint32_t* CH = (uint32_t*)(sm + O_CH);
    uint32_t* CL = (uint32_t*)(sm + O_CL);
    float* As  = (float*)(sm + O_AS);
    float* x2s = (float*)(sm + O_X2);
    float* ps  = (float*)(sm + O_PS);
    float* p1  = (float*)(sm + O_P1);
    float* p2  = (float*)(sm + O_P2);
    float* p3  = (float*)(sm + O_P3);
    float* SkS = (float*)(sm + O_SKS);
    float* Sk  = (float*)(sm + O_SK);

    const int t = threadIdx.x, lane = t & 31, w = t >> 5;   // w: 0..15
    const int gid = lane >> 2, tig = lane & 3;
    const int b = blockIdx.y, chunk = blockIdx.x;

    // ================= stage: x -> XH/XL (tf32 hi/lo), c -> CH/CL; x2/c2 free =================
    {
        const float4* xg = (const float4*)(x + ((size_t)b * NPIX + chunk * ROWS_CTA) * DD);
        const float4* cg = (const float4*)cw;
        float q[8], qc[2];
        #pragma unroll
        for (int p = 0; p < 8; p++) {
            float4 v = xg[p * NTHREADS + t];            // row = 16p + w, col = 4*lane
            int off = (16 * p + w) * STR + 4 * lane;
            uint4 h, l;
            h.x = tf32c(v.x); h.y = tf32c(v.y); h.z = tf32c(v.z); h.w = tf32c(v.w);
            l.x = tf32c(v.x - __uint_as_float(h.x));
            l.y = tf32c(v.y - __uint_as_float(h.y));
            l.z = tf32c(v.z - __uint_as_float(h.z));
            l.w = tf32c(v.w - __uint_as_float(h.w));
            *(uint4*)&XH[off] = h;
            *(uint4*)&XL[off] = l;
            float s = v.x * v.x; s = fmaf(v.y, v.y, s);
            s = fmaf(v.z, v.z, s); q[p] = fmaf(v.w, v.w, s);
        }
        #pragma unroll
        for (int p = 0; p < 2; p++) {
            float4 v = cg[p * NTHREADS + t];            // k = 16p + w, col = 4*lane
            int off = (16 * p + w) * STR + 4 * lane;
            uint4 h, l;
            h.x = tf32c(v.x); h.y = tf32c(v.y); h.z = tf32c(v.z); h.w = tf32c(v.w);
            l.x = tf32c(v.x - __uint_as_float(h.x));
            l.y = tf32c(v.y - __uint_as_float(h.y));
            l.z = tf32c(v.z - __uint_as_float(h.z));
            l.w = tf32c(v.w - __uint_as_float(h.w));
            *(uint4*)&CH[off] = h;
            *(uint4*)&CL[off] = l;
            float s = v.x * v.x; s = fmaf(v.y, v.y, s);
            s = fmaf(v.z, v.z, s); qc[p] = fmaf(v.w, v.w, s);
        }
        #pragma unroll
        for (int off = 16; off > 0; off >>= 1) {
            #pragma unroll
            for (int p = 0; p < 8; p++) q[p] += __shfl_xor_sync(0xffffffffu, q[p], off);
            #pragma unroll
            for (int p = 0; p < 2; p++) qc[p] += __shfl_xor_sync(0xffffffffu, qc[p], off);
        }
        if (lane == 0) {
            #pragma unroll
            for (int p = 0; p < 8; p++) x2s[16 * p + w] = q[p];
            #pragma unroll
            for (int p = 0; p < 2; p++) {
                int k = 16 * p + w;
                float s = scale[k];
                p1[k] = s; p2[k] = -2.f * s; p3[k] = s * qc[p];
            }
        }
    }
    __syncthreads();

    // ========== logits GEMM: 3xTF32 mma; warp = (rt row-tile, nth k-half) ==========
    {
        const int rt = w & 7, nth = w >> 3;
        const int r0 = 16 * rt + gid, r1 = r0 + 8;
        const int kb0 = 16 * nth + gid, kb1 = kb0 + 8;
        float dA[4] = {0,0,0,0}, dB[4] = {0,0,0,0}, dC[4] = {0,0,0,0};
        float eA[4] = {0,0,0,0}, eB[4] = {0,0,0,0}, eC[4] = {0,0,0,0};
        #pragma unroll
        for (int c = 0; c < 16; c++) {
            const int cb = c * 8;
            uint32_t ah0 = XH[r0 * STR + cb + tig],     ah1 = XH[r1 * STR + cb + tig];
            uint32_t ah2 = XH[r0 * STR + cb + tig + 4], ah3 = XH[r1 * STR + cb + tig + 4];
            uint32_t al0 = XL[r0 * STR + cb + tig],     al1 = XL[r1 * STR + cb + tig];
            uint32_t al2 = XL[r0 * STR + cb + tig + 4], al3 = XL[r1 * STR + cb + tig + 4];
            uint32_t bh0 = CH[kb0 * STR + cb + tig], bh1 = CH[kb0 * STR + cb + tig + 4];
            uint32_t bl0 = CL[kb0 * STR + cb + tig], bl1 = CL[kb0 * STR + cb + tig + 4];
            mma8(dA, ah0, ah1, ah2, ah3, bh0, bh1);
            mma8(dB, ah0, ah1, ah2, ah3, bl0, bl1);
            mma8(dC, al0, al1, al2, al3, bh0, bh1);
            bh0 = CH[kb1 * STR + cb + tig]; bh1 = CH[kb1 * STR + cb + tig + 4];
            bl0 = CL[kb1 * STR + cb + tig]; bl1 = CL[kb1 * STR + cb + tig + 4];
            mma8(eA, ah0, ah1, ah2, ah3, bh0, bh1);
            mma8(eB, ah0, ah1, ah2, ah3, bl0, bl1);
            mma8(eC, al0, al1, al2, al3, bh0, bh1);
        }
        float d0[4], d1[4];
        #pragma unroll
        for (int j = 0; j < 4; j++) {
            d0[j] = (dA[j] + dB[j]) + dC[j];
            d1[j] = (eA[j] + eB[j]) + eC[j];
        }
        // exp + half-row sums (no max-subtraction: scale<0, logits bounded;
        // validated rel_err ~2.5e-7 across rounds)
        const float x20 = x2s[r0], x21 = x2s[r1];
        float s0 = 0.f, s1 = 0.f;
        #pragma unroll
        for (int tt = 0; tt < 2; tt++) {
            const float* D = tt ? d1 : d0;
            #pragma unroll
            for (int p = 0; p < 2; p++) {
                int k = 16 * nth + 8 * tt + 2 * tig + p;
                float P1 = p1[k], P2 = p2[k], P3 = p3[k];
                float e0 = __expf(fmaf(P1, x20, fmaf(P2, D[p],     P3)));
                float e1 = __expf(fmaf(P1, x21, fmaf(P2, D[2 + p], P3)));
                As[r0 * AST + k] = e0;
                As[r1 * AST + k] = e1;
                s0 += e0; s1 += e1;
            }
        }
        s0 += __shfl_xor_sync(0xffffffffu, s0, 1);
        s0 += __shfl_xor_sync(0xffffffffu, s0, 2);
        s1 += __shfl_xor_sync(0xffffffffu, s1, 1);
        s1 += __shfl_xor_sync(0xffffffffu, s1, 2);
        if (tig == 0) { ps[r0 * 2 + nth] = s0; ps[r1 * 2 + nth] = s1; }
    }
    __syncthreads();

    // ======== normalize A in place + per-thread Sk partials (column = lane) ========
    {
        float skp = 0.f;
        #pragma unroll
        for (int j = 0; j < 8; j++) {
            int r = 16 * j + w;
            float rinv = __fdividef(1.f, ps[2 * r] + ps[2 * r + 1]);
            float a = As[r * AST + lane] * rinv;
            As[r * AST + lane] = a;
            skp += a;
        }
        SkS[w * 32 + lane] = skp;
    }
    __syncthreads();
    if (w == 0) {
        float s = 0.f;
        #pragma unroll
        for (int i = 0; i < 16; i++) s += SkS[i * 32 + lane];
        Sk[lane] = s;
    }
    __syncthreads();

    // ========== E GEMM: D[kk][d] = sum_r A[r][kk] * X[r][d], 3xTF32 mma ==========
    // warp = (mt = w>>3: kk-tile of 16, ng = w&7: d-group of 16)
    {
        const int mt = w >> 3, ng = w & 7;
        const int kk0 = 16 * mt + gid;           // A m-rows: kk0, kk0+8
        const int d0c = 16 * ng + gid;           // B n-cols: d0c (tile0), d0c+8 (tile1)
        float fA[4] = {0,0,0,0}, fB[4] = {0,0,0,0}, fC[4] = {0,0,0,0};
        float gA[4] = {0,0,0,0}, gB[4] = {0,0,0,0}, gC[4] = {0,0,0,0};
        #pragma unroll
        for (int s = 0; s < 16; s++) {
            const int rb = 8 * s;
            // A fragment: A[m=kk][k=r] = As[r][kk] ; hi/lo split on the fly
            float a0 = As[(rb + tig) * AST + kk0];
            float a1 = As[(rb + tig) * AST + kk0 + 8];
            float a2 = As[(rb + tig + 4) * AST + kk0];
            float a3 = As[(rb + tig + 4) * AST + kk0 + 8];
            uint32_t ah0 = tf32c(a0), ah1 = tf32c(a1), ah2 = tf32c(a2), ah3 = tf32c(a3);
            uint32_t al0 = tf32c(a0 - __uint_as_float(ah0));
            uint32_t al1 = tf32c(a1 - __uint_as_float(ah1));
            uint32_t al2 = tf32c(a2 - __uint_as_float(ah2));
            uint32_t al3 = tf32c(a3 - __uint_as_float(ah3));
            // B fragment: B[k=r][n=d] = X[r][d] (col-major thread map)
            uint32_t bh0 = XH[(rb + tig) * STR + d0c],     bh1 = XH[(rb + tig + 4) * STR + d0c];
            uint32_t bl0 = XL[(rb + tig) * STR + d0c],     bl1 = XL[(rb + tig + 4) * STR + d0c];
            mma8(fA, ah0, ah1, ah2, ah3, bh0, bh1);
            mma8(fB, ah0, ah1, ah2, ah3, bl0, bl1);
            mma8(fC, al0, al1, al2, al3, bh0, bh1);
            bh0 = XH[(rb + tig) * STR + d0c + 8]; bh1 = XH[(rb + tig + 4) * STR + d0c + 8];
            bl0 = XL[(rb + tig) * STR + d0c + 8]; bl1 = XL[(rb + tig + 4) * STR + d0c + 8];
            mma8(gA, ah0, ah1, ah2, ah3, bh0, bh1);
            mma8(gB, ah0, ah1, ah2, ah3, bl0, bl1);
            mma8(gC, al0, al1, al2, al3, bh0, bh1);
        }
        // combine + epilogue: out[(b*32+kk)*128+d] += D - Sk[kk]*c[kk][d]
        float v0[4], v1[4];
        #pragma unroll
        for (int j = 0; j < 4; j++) {
            v0[j] = (fA[j] + fB[j]) + fC[j];   // n-tile0: d = 16ng+2tig(+1)
            v1[j] = (gA[j] + gB[j]) + gC[j];   // n-tile1: d = 16ng+8+2tig(+1)
        }
        const float sk0 = Sk[kk0], sk1 = Sk[kk0 + 8];
        const int dd = 16 * ng + 2 * tig;
        const float* cb0 = cw + (size_t)kk0 * DD;
        const float* cb1 = cw + (size_t)(kk0 + 8) * DD;
        float* ob0 = out + ((size_t)(b * KK + kk0)) * DD;
        float* ob1 = out + ((size_t)(b * KK + kk0 + 8)) * DD;
        float2 c00 = *(const float2*)&cb0[dd];
        float2 c01 = *(const float2*)&cb0[dd + 8];
        float2 c10 = *(const float2*)&cb1[dd];
        float2 c11 = *(const float2*)&cb1[dd + 8];
        red2(&ob0[dd],     fmaf(-sk0, c00.x, v0[0]), fmaf(-sk0, c00.y, v0[1]));
        red2(&ob0[dd + 8], fmaf(-sk0, c01.x, v1[0]), fmaf(-sk0, c01.y, v1[1]));
        red2(&ob1[dd],     fmaf(-sk1, c10.x, v0[2]), fmaf(-sk1, c10.y, v0[3]));
        red2(&ob1[dd + 8], fmaf(-sk1, c11.x, v1[2]), fmaf(-sk1, c11.y, v1[3]));
    }
}

extern "C" void kernel_launch(void* const* d_in, const int* in_sizes, int n_in,
                              void* d_out, int out_size) {
    const float* x  = (const float*)d_in[0];
    const float* cw = (const float*)d_in[1];
    const float* sc = (const float*)d_in[2];
    float* out = (float*)d_out;

    cudaFuncSetAttribute(enc_kernel, cudaFuncAttributeMaxDynamicSharedMemorySize, SMEM_TOTAL);

    int n4 = out_size / 4;
    zero_kernel<<<(n4 + 255) / 256, 256>>>((float4*)out, n4);

    dim3 grid(CHUNKS, BB);
    enc_kernel<<<grid, NTHREADS, SMEM_TOTAL>>>(x, cw, sc, out);
}